// round 4
// baseline (speedup 1.0000x reference)
#include <cuda_runtime.h>
#include <cuda_bf16.h>
#include <cstdint>

#define MAX_N 100000
#define MAX_E 1250000
#define D 64
#define SCAN_BLK 2048
#define MAX_SCAN_BLKS 64
#define TN 32                       // nodes per transform block
// smem: sWld 32K | sWrd 32K | sMt 8K | sXt 8K | sB 256B
#define XFORM_SMEM_FLOATS (8192 + 8192 + 2048 + 2048 + 64)
#define XFORM_SMEM_BYTES (XFORM_SMEM_FLOATS * 4)

// Scratch (device globals; no allocation allowed).
__device__ float g_mean[MAX_N * D];
__device__ float g_h[MAX_N * D];
__device__ int   g_cnt[MAX_N];
__device__ int   g_off[MAX_N];
__device__ int   g_pos[MAX_N];
__device__ int   g_csr[MAX_E];
__device__ int   g_blk[MAX_SCAN_BLKS];

// ---------------------------------------------------------------------------
__global__ void zero_int_kernel(int* __restrict__ p, int n) {
    int i = blockIdx.x * blockDim.x + threadIdx.x;
    if (i < n) p[i] = 0;
}

__global__ void hist_kernel(const int* __restrict__ ei, int* __restrict__ cnt, int E) {
    int e = blockIdx.x * blockDim.x + threadIdx.x;
    if (e < E) atomicAdd(&cnt[ei[E + e]], 1);
}

__global__ __launch_bounds__(256)
void scan_k1(const int* __restrict__ cnt, int* __restrict__ off,
             int* __restrict__ blk, int n) {
    __shared__ int warp_excl[8];
    int t = threadIdx.x;
    int lane = t & 31, w = t >> 5;
    int base = blockIdx.x * SCAN_BLK + t * 8;
    int v[8];
    int s = 0;
#pragma unroll
    for (int q = 0; q < 8; q++) {
        int idx = base + q;
        v[q] = (idx < n) ? cnt[idx] : 0;
        s += v[q];
    }
    int ps = s;
#pragma unroll
    for (int d = 1; d < 32; d <<= 1) {
        int o = __shfl_up_sync(0xffffffffu, ps, d);
        if (lane >= d) ps += o;
    }
    if (lane == 31) warp_excl[w] = ps;
    __syncthreads();
    if (w == 0 && lane < 8) {
        int ws = warp_excl[lane];
        int pw = ws;
#pragma unroll
        for (int d = 1; d < 8; d <<= 1) {
            int o = __shfl_up_sync(0xffu, pw, d);
            if (lane >= d) pw += o;
        }
        warp_excl[lane] = pw - ws;
    }
    __syncthreads();
    int excl = warp_excl[w] + (ps - s);
    int run = excl;
#pragma unroll
    for (int q = 0; q < 8; q++) {
        int idx = base + q;
        if (idx < n) off[idx] = run;
        run += v[q];
    }
    if (t == 255) blk[blockIdx.x] = excl + s;
}

__global__ void scan_k2(int* __restrict__ blk, int nb) {
    __shared__ int sm[MAX_SCAN_BLKS];
    int t = threadIdx.x;
    int v = (t < nb) ? blk[t] : 0;
    sm[t] = v;
    __syncthreads();
    for (int d = 1; d < MAX_SCAN_BLKS; d <<= 1) {
        int o = (t >= d) ? sm[t - d] : 0;
        __syncthreads();
        sm[t] += o;
        __syncthreads();
    }
    if (t < nb) blk[t] = sm[t] - v;
}

__global__ void scan_k3(int* __restrict__ off, const int* __restrict__ blk,
                        int* __restrict__ pos, int n) {
    int i = blockIdx.x * blockDim.x + threadIdx.x;
    if (i < n) {
        int o = off[i] + blk[i >> 11];
        off[i] = o;
        pos[i] = o;
    }
}

__global__ void fill_kernel(const int* __restrict__ ei, int* __restrict__ pos,
                            int* __restrict__ csr, int E) {
    int e = blockIdx.x * blockDim.x + threadIdx.x;
    if (e < E) {
        int dst = ei[E + e];
        int p = atomicAdd(&pos[dst], 1);
        csr[p] = ei[e];
    }
}

// ---------------------------------------------------------------------------
// Aggregate: mean[node] = (1/max(cnt,1)) * sum_{i in CSR[node]} x[csr[i]]
// 16 threads per node, each owns one float4 chunk. No atomics.
// ---------------------------------------------------------------------------
__global__ __launch_bounds__(256)
void aggregate_kernel(const float4* __restrict__ x4,
                      const int* __restrict__ off,
                      const int* __restrict__ cnt,
                      const int* __restrict__ csr,
                      float4* __restrict__ mean4, int n) {
    int tid = blockIdx.x * blockDim.x + threadIdx.x;
    int node = tid >> 4;
    if (node >= n) return;
    int j = tid & 15;
    int s = off[node];
    int c = cnt[node];
    int e = s + c;

    float4 a0 = make_float4(0.f, 0.f, 0.f, 0.f);
    float4 a1 = make_float4(0.f, 0.f, 0.f, 0.f);
    int i = s;
    for (; i + 2 <= e; i += 2) {
        int s0 = csr[i];
        int s1 = csr[i + 1];
        float4 v0 = x4[s0 * 16 + j];
        float4 v1 = x4[s1 * 16 + j];
        a0.x += v0.x; a0.y += v0.y; a0.z += v0.z; a0.w += v0.w;
        a1.x += v1.x; a1.y += v1.y; a1.z += v1.z; a1.w += v1.w;
    }
    if (i < e) {
        float4 v = x4[csr[i] * 16 + j];
        a0.x += v.x; a0.y += v.y; a0.z += v.z; a0.w += v.w;
    }
    float inv = 1.0f / fmaxf((float)c, 1.0f);
    a0.x = (a0.x + a1.x) * inv;
    a0.y = (a0.y + a1.y) * inv;
    a0.z = (a0.z + a1.z) * inv;
    a0.w = (a0.w + a1.w) * inv;
    mean4[node * 16 + j] = a0;
}

// ---------------------------------------------------------------------------
// Packed f32x2 FMA (FFMA2): d = a * b + d, elementwise on packed pairs.
// ---------------------------------------------------------------------------
__device__ __forceinline__ void fma2(uint64_t& d, uint64_t a, uint64_t b) {
    asm("fma.rn.f32x2 %0, %1, %2, %0;" : "+l"(d) : "l"(a), "l"(b));
}

__device__ __forceinline__ uint64_t pack2(float lo, float hi) {
    float2 f = make_float2(lo, hi);
    return *(uint64_t*)&f;
}

// ---------------------------------------------------------------------------
// Transform: out[i] = act( mean[i] @ W_l + b_l + xin[i] @ W_r )
// 32 nodes/block, 128 threads. Thread = 4 contiguous nodes x 4 cols.
// FMA2 packs NODE PAIRS: acc[c][p] = ((node 2p, node 2p+1) @ col c).
// Weights staged DUPLICATED ((w,w) pairs) once per block; node rows staged
// plain-transposed [k][node] (cheap, conflict-free, same as the R2 kernel).
// Inner loop per k: 6x LDS.128 (24 cyc/warp) + 16 FMA2 (32 cyc) -> FMA2-bound.
// ---------------------------------------------------------------------------
__global__ __launch_bounds__(128)
void transform_kernel(const float* __restrict__ xin,
                      const float* __restrict__ mean,
                      const float* __restrict__ Wl,
                      const float* __restrict__ bl,
                      const float* __restrict__ Wr,
                      float* __restrict__ out,
                      int n, int do_relu) {
    extern __shared__ float smem[];
    float* sWld = smem;              // 8192 floats: [k][2c] duplicated
    float* sWrd = smem + 8192;       // 8192
    float* sMt  = smem + 16384;      // 64 * 32, [k][node]
    float* sXt  = smem + 18432;      // 64 * 32
    float* sB   = smem + 20480;      // 64

    int t = threadIdx.x;
    // Stage duplicated weights: element pair i covers W[k][2c..2c+1].
    for (int i = t; i < 2048; i += 128) {
        float2 wl = ((const float2*)Wl)[i];
        float2 wr = ((const float2*)Wr)[i];
        ((float4*)sWld)[i] = make_float4(wl.x, wl.x, wl.y, wl.y);
        ((float4*)sWrd)[i] = make_float4(wr.x, wr.x, wr.y, wr.y);
    }
    if (t < D) sB[t] = bl[t];

    int base = blockIdx.x * TN;
    // Stage 32 nodes x 16 float4 chunks, transposed into [k][node].
    for (int i = t; i < TN * 16; i += 128) {
        int local = i & (TN - 1);
        int j = i >> 5;                 // chunk: k = 4j..4j+3
        int node = base + local;
        float4 mv, xv;
        if (node < n) {
            mv = ((const float4*)mean)[node * 16 + j];
            xv = ((const float4*)xin)[node * 16 + j];
        } else {
            mv = make_float4(0.f, 0.f, 0.f, 0.f);
            xv = mv;
        }
        sMt[(4 * j + 0) * TN + local] = mv.x;
        sMt[(4 * j + 1) * TN + local] = mv.y;
        sMt[(4 * j + 2) * TN + local] = mv.z;
        sMt[(4 * j + 3) * TN + local] = mv.w;
        sXt[(4 * j + 0) * TN + local] = xv.x;
        sXt[(4 * j + 1) * TN + local] = xv.y;
        sXt[(4 * j + 2) * TN + local] = xv.z;
        sXt[(4 * j + 3) * TN + local] = xv.w;
    }
    __syncthreads();

    int cg = t & 15;         // column group: cols 4*cg .. 4*cg+3
    int ng = t >> 4;         // node group 0..7: nodes 4*ng .. 4*ng+3
    int c0 = cg * 4;
    int nb = ng * 4;

    // acc[c][p]: packed (node nb+2p, node nb+2p+1) at column c0+c.
    uint64_t acc[4][2];
#pragma unroll
    for (int c = 0; c < 4; c++) {
        uint64_t b2 = pack2(sB[c0 + c], sB[c0 + c]);
        acc[c][0] = b2;
        acc[c][1] = b2;
    }

#pragma unroll
    for (int k = 0; k < D; k++) {
        // Duplicated weight pairs for 4 cols: 8 floats at [k][2*c0].
        ulonglong2 wl01 = *(const ulonglong2*)&sWld[k * 128 + 2 * c0];
        ulonglong2 wl23 = *(const ulonglong2*)&sWld[k * 128 + 2 * c0 + 4];
        ulonglong2 wr01 = *(const ulonglong2*)&sWrd[k * 128 + 2 * c0];
        ulonglong2 wr23 = *(const ulonglong2*)&sWrd[k * 128 + 2 * c0 + 4];
        // Node pairs: 4 contiguous nodes -> (m0,m1),(m2,m3).
        ulonglong2 m2 = *(const ulonglong2*)&sMt[k * TN + nb];
        ulonglong2 x2 = *(const ulonglong2*)&sXt[k * TN + nb];

        fma2(acc[0][0], m2.x, wl01.x);  fma2(acc[0][1], m2.y, wl01.x);
        fma2(acc[1][0], m2.x, wl01.y);  fma2(acc[1][1], m2.y, wl01.y);
        fma2(acc[2][0], m2.x, wl23.x);  fma2(acc[2][1], m2.y, wl23.x);
        fma2(acc[3][0], m2.x, wl23.y);  fma2(acc[3][1], m2.y, wl23.y);
        fma2(acc[0][0], x2.x, wr01.x);  fma2(acc[0][1], x2.y, wr01.x);
        fma2(acc[1][0], x2.x, wr01.y);  fma2(acc[1][1], x2.y, wr01.y);
        fma2(acc[2][0], x2.x, wr23.x);  fma2(acc[2][1], x2.y, wr23.x);
        fma2(acc[3][0], x2.x, wr23.y);  fma2(acc[3][1], x2.y, wr23.y);
    }

#pragma unroll
    for (int p = 0; p < 2; p++) {
        float2 a0 = *(float2*)&acc[0][p];
        float2 a1 = *(float2*)&acc[1][p];
        float2 a2 = *(float2*)&acc[2][p];
        float2 a3 = *(float2*)&acc[3][p];
        float4 r0 = make_float4(a0.x, a1.x, a2.x, a3.x);  // node nb+2p
        float4 r1 = make_float4(a0.y, a1.y, a2.y, a3.y);  // node nb+2p+1
        if (do_relu) {
            r0.x = fmaxf(r0.x, 0.f); r0.y = fmaxf(r0.y, 0.f);
            r0.z = fmaxf(r0.z, 0.f); r0.w = fmaxf(r0.w, 0.f);
            r1.x = fmaxf(r1.x, 0.f); r1.y = fmaxf(r1.y, 0.f);
            r1.z = fmaxf(r1.z, 0.f); r1.w = fmaxf(r1.w, 0.f);
        }
        int node0 = base + nb + 2 * p;
        int node1 = node0 + 1;
        if (node0 < n) *(float4*)&out[node0 * D + c0] = r0;
        if (node1 < n) *(float4*)&out[node1 * D + c0] = r1;
    }
}

// ---------------------------------------------------------------------------
extern "C" void kernel_launch(void* const* d_in, const int* in_sizes, int n_in,
                              void* d_out, int out_size) {
    const float* x   = (const float*)d_in[0];
    const int*   ei  = (const int*)d_in[1];
    const float* Wl1 = (const float*)d_in[2];
    const float* bl1 = (const float*)d_in[3];
    const float* Wr1 = (const float*)d_in[4];
    const float* Wl2 = (const float*)d_in[5];
    const float* bl2 = (const float*)d_in[6];
    const float* Wr2 = (const float*)d_in[7];
    float* out = (float*)d_out;

    int N = in_sizes[0] / D;   // 100000
    int E = in_sizes[1] / 2;   // 1250000

    float *mean, *h;
    int *cnt, *off, *pos, *csr, *blk;
    cudaGetSymbolAddress((void**)&mean, g_mean);
    cudaGetSymbolAddress((void**)&h,    g_h);
    cudaGetSymbolAddress((void**)&cnt,  g_cnt);
    cudaGetSymbolAddress((void**)&off,  g_off);
    cudaGetSymbolAddress((void**)&pos,  g_pos);
    cudaGetSymbolAddress((void**)&csr,  g_csr);
    cudaGetSymbolAddress((void**)&blk,  g_blk);

    cudaFuncSetAttribute(transform_kernel,
                         cudaFuncAttributeMaxDynamicSharedMemorySize,
                         XFORM_SMEM_BYTES);

    int nb_scan = (N + SCAN_BLK - 1) / SCAN_BLK;

    // ---- CSR build (once; reused by both layers) ----
    zero_int_kernel<<<(N + 255) / 256, 256>>>(cnt, N);
    hist_kernel<<<(E + 255) / 256, 256>>>(ei, cnt, E);
    scan_k1<<<nb_scan, 256>>>(cnt, off, blk, N);
    scan_k2<<<1, MAX_SCAN_BLKS>>>(blk, nb_scan);
    scan_k3<<<(N + 255) / 256, 256>>>(off, blk, pos, N);
    fill_kernel<<<(E + 255) / 256, 256>>>(ei, pos, csr, E);

    int ab = (N * 16 + 255) / 256;
    int tb = (N + TN - 1) / TN;

    // ---- Layer 1 ----
    aggregate_kernel<<<ab, 256>>>((const float4*)x, off, cnt, csr,
                                  (float4*)mean, N);
    transform_kernel<<<tb, 128, XFORM_SMEM_BYTES>>>(x, mean, Wl1, bl1, Wr1, h, N, 1);

    // ---- Layer 2 ----
    aggregate_kernel<<<ab, 256>>>((const float4*)h, off, cnt, csr,
                                  (float4*)mean, N);
    transform_kernel<<<tb, 128, XFORM_SMEM_BYTES>>>(h, mean, Wl2, bl2, Wr2, out, N, 0);
}

// round 6
// speedup vs baseline: 2.0804x; 2.0804x over previous
#include <cuda_runtime.h>
#include <cuda_bf16.h>
#include <cstdint>

#define MAX_N 100000
#define MAX_E 1250000
#define D 64
#define SCAN_BLK 2048
#define MAX_SCAN_BLKS 64

// ---------------- GEMM smem layout (bytes) ----------------
// A chunks: 128 rows x 72 bf16 (144B padded stride) = 18432B each.
// B mats:   64 rows x 72 bf16 = 9216B each (Wl_hi, Wl_lo, Wr_hi, Wr_lo).
#define SM_AMH  0
#define SM_AML  18432
#define SM_AXH  36864
#define SM_AXL  55296
#define SM_B    73728
#define SM_BIAS 110592
#define GEMM_SMEM 110848
#define APAD 144   // bytes per padded A/B row

// Scratch (device globals; no allocation allowed).
__device__ float g_mean[MAX_N * D];
__device__ float g_h[MAX_N * D];
__device__ int   g_cnt[MAX_N];
__device__ int   g_off[MAX_N];
__device__ int   g_pos[MAX_N];
__device__ int   g_csr[MAX_E];
__device__ int   g_blk[MAX_SCAN_BLKS];
// Weight images: [layer][Wl_hi | Wl_lo | Wr_hi | Wr_lo][n*64+k] bf16, B[n][k] = W[k][n]
__device__ unsigned short g_wt[2][4 * 4096];

// ---------------------------------------------------------------------------
__device__ __forceinline__ uint32_t smem_u32(const void* p) {
    uint32_t a;
    asm("{ .reg .u64 t; cvta.to.shared.u64 t, %1; cvt.u32.u64 %0, t; }"
        : "=r"(a) : "l"(p));
    return a;
}
__device__ __forceinline__ void ldsm_x4(uint32_t& r0, uint32_t& r1,
                                        uint32_t& r2, uint32_t& r3,
                                        uint32_t addr) {
    asm volatile("ldmatrix.sync.aligned.m8n8.x4.shared.b16 {%0,%1,%2,%3}, [%4];"
                 : "=r"(r0), "=r"(r1), "=r"(r2), "=r"(r3) : "r"(addr));
}
__device__ __forceinline__ void mma_bf16(float* c, const uint32_t* a,
                                         uint32_t b0, uint32_t b1) {
    asm volatile("mma.sync.aligned.m16n8k16.row.col.f32.bf16.bf16.f32 "
                 "{%0,%1,%2,%3}, {%4,%5,%6,%7}, {%8,%9}, {%0,%1,%2,%3};"
                 : "+f"(c[0]), "+f"(c[1]), "+f"(c[2]), "+f"(c[3])
                 : "r"(a[0]), "r"(a[1]), "r"(a[2]), "r"(a[3]),
                   "r"(b0), "r"(b1));
}
__device__ __forceinline__ void split2(float v, unsigned short& h, unsigned short& l) {
    __nv_bfloat16 hb = __float2bfloat16(v);
    float r = v - __bfloat162float(hb);
    __nv_bfloat16 lb = __float2bfloat16(r);
    h = *(unsigned short*)&hb;
    l = *(unsigned short*)&lb;
}

// ---------------------------------------------------------------------------
// CSR build (unchanged from R2)
// ---------------------------------------------------------------------------
__global__ void zero_int_kernel(int* __restrict__ p, int n) {
    int i = blockIdx.x * blockDim.x + threadIdx.x;
    if (i < n) p[i] = 0;
}
__global__ void hist_kernel(const int* __restrict__ ei, int* __restrict__ cnt, int E) {
    int e = blockIdx.x * blockDim.x + threadIdx.x;
    if (e < E) atomicAdd(&cnt[ei[E + e]], 1);
}
__global__ __launch_bounds__(256)
void scan_k1(const int* __restrict__ cnt, int* __restrict__ off,
             int* __restrict__ blk, int n) {
    __shared__ int warp_excl[8];
    int t = threadIdx.x;
    int lane = t & 31, w = t >> 5;
    int base = blockIdx.x * SCAN_BLK + t * 8;
    int v[8];
    int s = 0;
#pragma unroll
    for (int q = 0; q < 8; q++) {
        int idx = base + q;
        v[q] = (idx < n) ? cnt[idx] : 0;
        s += v[q];
    }
    int ps = s;
#pragma unroll
    for (int d = 1; d < 32; d <<= 1) {
        int o = __shfl_up_sync(0xffffffffu, ps, d);
        if (lane >= d) ps += o;
    }
    if (lane == 31) warp_excl[w] = ps;
    __syncthreads();
    if (w == 0 && lane < 8) {
        int ws = warp_excl[lane];
        int pw = ws;
#pragma unroll
        for (int d = 1; d < 8; d <<= 1) {
            int o = __shfl_up_sync(0xffu, pw, d);
            if (lane >= d) pw += o;
        }
        warp_excl[lane] = pw - ws;
    }
    __syncthreads();
    int excl = warp_excl[w] + (ps - s);
    int run = excl;
#pragma unroll
    for (int q = 0; q < 8; q++) {
        int idx = base + q;
        if (idx < n) off[idx] = run;
        run += v[q];
    }
    if (t == 255) blk[blockIdx.x] = excl + s;
}
__global__ void scan_k2(int* __restrict__ blk, int nb) {
    __shared__ int sm[MAX_SCAN_BLKS];
    int t = threadIdx.x;
    int v = (t < nb) ? blk[t] : 0;
    sm[t] = v;
    __syncthreads();
    for (int d = 1; d < MAX_SCAN_BLKS; d <<= 1) {
        int o = (t >= d) ? sm[t - d] : 0;
        __syncthreads();
        sm[t] += o;
        __syncthreads();
    }
    if (t < nb) blk[t] = sm[t] - v;
}
__global__ void scan_k3(int* __restrict__ off, const int* __restrict__ blk,
                        int* __restrict__ pos, int n) {
    int i = blockIdx.x * blockDim.x + threadIdx.x;
    if (i < n) {
        int o = off[i] + blk[i >> 11];
        off[i] = o;
        pos[i] = o;
    }
}
__global__ void fill_kernel(const int* __restrict__ ei, int* __restrict__ pos,
                            int* __restrict__ csr, int E) {
    int e = blockIdx.x * blockDim.x + threadIdx.x;
    if (e < E) {
        int dst = ei[E + e];
        int p = atomicAdd(&pos[dst], 1);
        csr[p] = ei[e];
    }
}

// ---------------------------------------------------------------------------
// Aggregate (unchanged from R2)
// ---------------------------------------------------------------------------
__global__ __launch_bounds__(256)
void aggregate_kernel(const float4* __restrict__ x4,
                      const int* __restrict__ off,
                      const int* __restrict__ cnt,
                      const int* __restrict__ csr,
                      float4* __restrict__ mean4, int n) {
    int tid = blockIdx.x * blockDim.x + threadIdx.x;
    int node = tid >> 4;
    if (node >= n) return;
    int j = tid & 15;
    int s = off[node];
    int c = cnt[node];
    int e = s + c;

    float4 a0 = make_float4(0.f, 0.f, 0.f, 0.f);
    float4 a1 = make_float4(0.f, 0.f, 0.f, 0.f);
    int i = s;
    for (; i + 2 <= e; i += 2) {
        int s0 = csr[i];
        int s1 = csr[i + 1];
        float4 v0 = x4[s0 * 16 + j];
        float4 v1 = x4[s1 * 16 + j];
        a0.x += v0.x; a0.y += v0.y; a0.z += v0.z; a0.w += v0.w;
        a1.x += v1.x; a1.y += v1.y; a1.z += v1.z; a1.w += v1.w;
    }
    if (i < e) {
        float4 v = x4[csr[i] * 16 + j];
        a0.x += v.x; a0.y += v.y; a0.z += v.z; a0.w += v.w;
    }
    float inv = 1.0f / fmaxf((float)c, 1.0f);
    a0.x = (a0.x + a1.x) * inv;
    a0.y = (a0.y + a1.y) * inv;
    a0.z = (a0.z + a1.z) * inv;
    a0.w = (a0.w + a1.w) * inv;
    mean4[node * 16 + j] = a0;
}

// ---------------------------------------------------------------------------
// Weight prep: B[n][k] = W[k][n], hi/lo bf16 split, into g_wt.
// slot: 0=Wl_hi 1=Wl_lo 2=Wr_hi 3=Wr_lo.
// ---------------------------------------------------------------------------
__global__ void prep_weights(const float* __restrict__ Wl1,
                             const float* __restrict__ Wr1,
                             const float* __restrict__ Wl2,
                             const float* __restrict__ Wr2) {
    int i = blockIdx.x * blockDim.x + threadIdx.x;   // 0 .. 16383
    if (i >= 2 * 2 * 64 * 64) return;
    int k = i & 63;
    int nn = (i >> 6) & 63;
    int mat = (i >> 12) & 1;     // 0 = Wl, 1 = Wr
    int layer = (i >> 13) & 1;
    const float* W = (layer == 0) ? (mat == 0 ? Wl1 : Wr1)
                                  : (mat == 0 ? Wl2 : Wr2);
    float v = W[k * 64 + nn];
    unsigned short h, l;
    split2(v, h, l);
    g_wt[layer][(mat * 2 + 0) * 4096 + nn * 64 + k] = h;
    g_wt[layer][(mat * 2 + 1) * 4096 + nn * 64 + k] = l;
}

// ---------------------------------------------------------------------------
// Tensor-core transform via mma.sync m16n8k16 bf16 (3-product split):
//   out = act( mean @ Wl + bl + xin @ Wr )
// CTA = 128 nodes, 256 threads (8 warps); warp = 16 rows x 64 cols.
// ---------------------------------------------------------------------------
__global__ __launch_bounds__(256)
void gemm_transform(const float* __restrict__ xin,
                    const float* __restrict__ mean,
                    const unsigned short* __restrict__ wt,
                    const float* __restrict__ bl,
                    float* __restrict__ out,
                    int n, int do_relu) {
    extern __shared__ char smem[];
    uint32_t sb = smem_u32(smem);
    int t = threadIdx.x;
    int wid = t >> 5;
    int lane = t & 31;
    int base = blockIdx.x * 128;

    // --- Stage weights (pad 128B rows -> 144B stride) + bias ---
    {
        int mat = t >> 6;          // 0..3
        int nrow = t & 63;
        const uint4* src = (const uint4*)(wt + mat * 4096 + nrow * 64);
        uint4* dst = (uint4*)(smem + SM_B + mat * 9216 + nrow * APAD);
#pragma unroll
        for (int q = 0; q < 8; q++) dst[q] = src[q];
    }
    if (t < 64) ((float*)(smem + SM_BIAS))[t] = bl[t];

    // --- Stage A: row = t/2, half = t&1 covers 8 float4 chunks per matrix ---
    {
        int row = t >> 1;
        int node = base + row;
        bool valid = node < n;
        int j0 = (t & 1) * 8;
        const float4* mr = (const float4*)mean + (size_t)node * 16;
        const float4* xr = (const float4*)xin + (size_t)node * 16;
#pragma unroll
        for (int j = j0; j < j0 + 8; j++) {
            float4 mv = valid ? mr[j] : make_float4(0.f, 0.f, 0.f, 0.f);
            float4 xv = valid ? xr[j] : make_float4(0.f, 0.f, 0.f, 0.f);
            unsigned short h0, h1, h2, h3, l0, l1, l2, l3;
            int boff = row * APAD + j * 8;
            split2(mv.x, h0, l0); split2(mv.y, h1, l1);
            split2(mv.z, h2, l2); split2(mv.w, h3, l3);
            *(uint2*)(smem + SM_AMH + boff) =
                make_uint2((uint32_t)h0 | ((uint32_t)h1 << 16),
                           (uint32_t)h2 | ((uint32_t)h3 << 16));
            *(uint2*)(smem + SM_AML + boff) =
                make_uint2((uint32_t)l0 | ((uint32_t)l1 << 16),
                           (uint32_t)l2 | ((uint32_t)l3 << 16));
            split2(xv.x, h0, l0); split2(xv.y, h1, l1);
            split2(xv.z, h2, l2); split2(xv.w, h3, l3);
            *(uint2*)(smem + SM_AXH + boff) =
                make_uint2((uint32_t)h0 | ((uint32_t)h1 << 16),
                           (uint32_t)h2 | ((uint32_t)h3 << 16));
            *(uint2*)(smem + SM_AXL + boff) =
                make_uint2((uint32_t)l0 | ((uint32_t)l1 << 16),
                           (uint32_t)l2 | ((uint32_t)l3 << 16));
        }
    }
    __syncthreads();

    // --- MMA mainloop: 6 products x 4 ksteps x 8 n-tiles ---
    const uint32_t paOff[6] = {SM_AMH, SM_AMH, SM_AML, SM_AXH, SM_AXH, SM_AXL};
    const uint32_t pbOff[6] = {SM_B + 0 * 9216, SM_B + 1 * 9216, SM_B + 0 * 9216,
                               SM_B + 2 * 9216, SM_B + 3 * 9216, SM_B + 2 * 9216};

    int wrow = wid * 16;
    // per-lane ldmatrix address components
    uint32_t a_row = wrow + (lane & 7) + ((lane >> 3) & 1) * 8;
    uint32_t a_colb = ((lane >> 4) * 8) * 2;                   // byte
    uint32_t a_base_off = a_row * APAD + a_colb;
    uint32_t b_row = ((lane >> 4) * 8 + (lane & 7));
    uint32_t b_colb = (((lane >> 3) & 1) * 8) * 2;
    uint32_t b_base_off = b_row * APAD + b_colb;

    float acc[8][4];
#pragma unroll
    for (int j = 0; j < 8; j++)
#pragma unroll
        for (int q = 0; q < 4; q++) acc[j][q] = 0.f;

#pragma unroll
    for (int p = 0; p < 6; p++) {
        uint32_t aBase = sb + paOff[p] + a_base_off;
        uint32_t bBase = sb + pbOff[p] + b_base_off;
#pragma unroll
        for (int k = 0; k < 4; k++) {
            uint32_t a[4];
            ldsm_x4(a[0], a[1], a[2], a[3], aBase + k * 32);
#pragma unroll
            for (int jj = 0; jj < 4; jj++) {
                uint32_t b0, b1, b2, b3;
                ldsm_x4(b0, b1, b2, b3, bBase + jj * 16 * APAD + k * 32);
                mma_bf16(acc[2 * jj],     a, b0, b1);
                mma_bf16(acc[2 * jj + 1], a, b2, b3);
            }
        }
    }

    // --- Epilogue: bias + relu + store ---
    const float* bias = (const float*)(smem + SM_BIAS);
    int r0 = base + wrow + (lane >> 2);
    int r1 = r0 + 8;
    int ctig = 2 * (lane & 3);
#pragma unroll
    for (int j = 0; j < 8; j++) {
        int col = 8 * j + ctig;
        float bx = bias[col], by = bias[col + 1];
        float2 v0 = make_float2(acc[j][0] + bx, acc[j][1] + by);
        float2 v1 = make_float2(acc[j][2] + bx, acc[j][3] + by);
        if (do_relu) {
            v0.x = fmaxf(v0.x, 0.f); v0.y = fmaxf(v0.y, 0.f);
            v1.x = fmaxf(v1.x, 0.f); v1.y = fmaxf(v1.y, 0.f);
        }
        if (r0 < n) *(float2*)&out[(size_t)r0 * 64 + col] = v0;
        if (r1 < n) *(float2*)&out[(size_t)r1 * 64 + col] = v1;
    }
}

// ---------------------------------------------------------------------------
extern "C" void kernel_launch(void* const* d_in, const int* in_sizes, int n_in,
                              void* d_out, int out_size) {
    const float* x   = (const float*)d_in[0];
    const int*   ei  = (const int*)d_in[1];
    const float* Wl1 = (const float*)d_in[2];
    const float* bl1 = (const float*)d_in[3];
    const float* Wr1 = (const float*)d_in[4];
    const float* Wl2 = (const float*)d_in[5];
    const float* bl2 = (const float*)d_in[6];
    const float* Wr2 = (const float*)d_in[7];
    float* out = (float*)d_out;

    int N = in_sizes[0] / D;   // 100000
    int E = in_sizes[1] / 2;   // 1250000

    float *mean, *h;
    int *cnt, *off, *pos, *csr, *blk;
    unsigned short* wt;
    cudaGetSymbolAddress((void**)&mean, g_mean);
    cudaGetSymbolAddress((void**)&h,    g_h);
    cudaGetSymbolAddress((void**)&cnt,  g_cnt);
    cudaGetSymbolAddress((void**)&off,  g_off);
    cudaGetSymbolAddress((void**)&pos,  g_pos);
    cudaGetSymbolAddress((void**)&csr,  g_csr);
    cudaGetSymbolAddress((void**)&blk,  g_blk);
    cudaGetSymbolAddress((void**)&wt,   g_wt);

    cudaFuncSetAttribute(gemm_transform,
                         cudaFuncAttributeMaxDynamicSharedMemorySize,
                         GEMM_SMEM);

    int nb_scan = (N + SCAN_BLK - 1) / SCAN_BLK;

    // ---- Weight prep + CSR build (once; reused by both layers) ----
    prep_weights<<<(16384 + 255) / 256, 256>>>(Wl1, Wr1, Wl2, Wr2);
    zero_int_kernel<<<(N + 255) / 256, 256>>>(cnt, N);
    hist_kernel<<<(E + 255) / 256, 256>>>(ei, cnt, E);
    scan_k1<<<nb_scan, 256>>>(cnt, off, blk, N);
    scan_k2<<<1, MAX_SCAN_BLKS>>>(blk, nb_scan);
    scan_k3<<<(N + 255) / 256, 256>>>(off, blk, pos, N);
    fill_kernel<<<(E + 255) / 256, 256>>>(ei, pos, csr, E);

    int ab = (N * 16 + 255) / 256;
    int tb = (N + 127) / 128;

    // ---- Layer 1 ----
    aggregate_kernel<<<ab, 256>>>((const float4*)x, off, cnt, csr,
                                  (float4*)mean, N);
    gemm_transform<<<tb, 256, GEMM_SMEM>>>(x, mean, wt, bl1, h, N, 1);

    // ---- Layer 2 ----
    aggregate_kernel<<<ab, 256>>>((const float4*)h, off, cnt, csr,
                                  (float4*)mean, N);
    gemm_transform<<<tb, 256, GEMM_SMEM>>>(h, mean, wt + 4 * 4096, bl2, out, N, 0);
}